// round 14
// baseline (speedup 1.0000x reference)
#include <cuda_runtime.h>
#include <math.h>

// CAM_43344809951340 — factored-moment formulation, 2 lanes per sample.
// tanh(s z_i z_j) = sum_k q_k s^(2k+1) z_i^(2k+1) z_j^(2k+1)  (deg-9 odd fit)
//  => row sum = sum_k q'_k z_i^(2k+1) M_k,  M_k = sum_j z_j^(2k+1) W_j.
// Warp owns 16 samples; lane l handles sample l&15, half l>>4 (32 elements).
// Partial moments are combined across the lane pair with ONE shfl_xor(16)
// butterfly that simultaneously selects: half-0 keeps full Ma (output rows
// 0-31), half-1 keeps full Mv (rows 32-63). smem halves to ~18KB/block ->
// ~10 resident blocks (40 warps/SM, 2x R12); per-thread chain halves.
// Samples with max|z| > 4 (~4e-3) re-solved exactly inline (tanh.approx).

#define KP   5
#define ZMAX 4.0f
#define RSTR 68                   // smem row stride (floats): 64 data + 4 pad

struct Poly { float q[KP]; };

__constant__ float cW[128];       // interleaved {Wca[j], Wcv[j]} j=0..63

__device__ __forceinline__ float tanhfast(float x) {
    float y; asm("tanh.approx.f32 %0, %1;" : "=f"(y) : "f"(x));
    return y;
}

__global__ __launch_bounds__(128, 8)
void cam_poly_kernel(const float* __restrict__ f1, const float* __restrict__ f2,
                     float* __restrict__ out, int B, Poly pc)
{
    __shared__ float  rows[4][16 * RSTR];   // per-warp: 16 samples x 64
    __shared__ float2 wsh[64];              // {Wca[j], Wcv[j]}

    const int tid = threadIdx.x;
    const int wrp = tid >> 5;
    const int l   = tid & 31;

    if (tid < 64) wsh[tid] = ((const float2*)cW)[tid];
    __syncthreads();

    const int wbase = (blockIdx.x * 4 + wrp) * 16;
    if (wbase >= B) return;
    float* R = rows[wrp];
    const bool full = (wbase + 16 <= B);

    // ---- stage: coalesced LDG.128 -> smem rows (transpose) ----
    if (full) {
        const float4* s1 = (const float4*)(f1 + (size_t)wbase * 32);
        const float4* s2 = (const float4*)(f2 + (size_t)wbase * 32);
        #pragma unroll
        for (int c = 0; c < 4; c++) {
            int g = c * 32 + l;                  // float4 id: sample g>>3, part g&7
            *(float4*)&R[(g >> 3) * RSTR + (g & 7) * 4] = s1[g];
        }
        #pragma unroll
        for (int c = 0; c < 4; c++) {
            int g = c * 32 + l;
            *(float4*)&R[(g >> 3) * RSTR + 32 + (g & 7) * 4] = s2[g];
        }
    } else {
        for (int c = 0; c < 16; c++) {
            int b = wbase + c;
            bool v = b < B;
            R[c * RSTR + l]      = v ? f1[b * 32 + l] : 0.0f;
            R[c * RSTR + 32 + l] = v ? f2[b * 32 + l] : 0.0f;
        }
    }
    __syncwarp();

    const int s    = l & 15;                     // my sample (within warp)
    const int half = l >> 4;                     // 0: elements 0-31, 1: 32-63
    float* myrow = &R[s * RSTR + half * 32];

    float q[KP];
    #pragma unroll
    for (int k = 0; k < KP; k++) q[k] = pc.q[k];

    // ---- phase 1: partial moments over my 32 elements ----
    float Ma[KP], Mv[KP];
    #pragma unroll
    for (int k = 0; k < KP; k++) { Ma[k] = 0.0f; Mv[k] = 0.0f; }
    float mx = 0.0f;

    #pragma unroll
    for (int jq = 0; jq < 8; jq++) {
        float4 v4 = *(const float4*)&myrow[jq * 4];
        float4 wA = *(const float4*)&wsh[half * 32 + jq * 4];      // {Wca,Wcv}x2
        float4 wB = *(const float4*)&wsh[half * 32 + jq * 4 + 2];
        const float vs[4] = {v4.x, v4.y, v4.z, v4.w};
        const float wx[4] = {wA.x, wA.z, wB.x, wB.z};
        const float wy[4] = {wA.y, wA.w, wB.y, wB.w};
        #pragma unroll
        for (int e = 0; e < 4; e++) {
            float v = vs[e];
            mx = fmaxf(mx, fabsf(v));
            float vv = v * v;
            float p = v;
            #pragma unroll
            for (int k = 0; k < KP; k++) {
                Ma[k] = fmaf(p, wx[e], Ma[k]);
                Mv[k] = fmaf(p, wy[e], Mv[k]);
                if (k < KP - 1) p *= vv;
            }
        }
    }

    // ---- butterfly: full moments + half-selection in one exchange ----
    // half-0 lane keeps full Ma (needs rows 0-31); half-1 keeps full Mv.
    float M[KP];
    #pragma unroll
    for (int k = 0; k < KP; k++) {
        float send = half ? Ma[k] : Mv[k];       // what my partner needs
        float recv = __shfl_xor_sync(0xffffffffu, send, 16);
        float mine = half ? Mv[k] : Ma[k];
        M[k] = (mine + recv) * q[k];
    }
    float mxf = fmaxf(mx, __shfl_xor_sync(0xffffffffu, mx, 16));

    // ---- phase 2: Horner for my 32 outputs, write back into row ----
    #pragma unroll
    for (int jq = 0; jq < 8; jq++) {
        float4 u4 = *(const float4*)&myrow[jq * 4];
        #pragma unroll
        for (int e = 0; e < 4; e++) {
            float u = (&u4.x)[e];
            float uu = u * u;
            float A = M[KP - 1];
            #pragma unroll
            for (int k = KP - 2; k >= 0; k--) A = fmaf(A, uu, M[k]);
            A += 0.1f;                           // folded residual 0.1*z
            (&u4.x)[e] = fmaxf(u * A, 0.0f);
        }
        *(float4*)&myrow[jq * 4] = u4;
    }
    __syncwarp();

    // ---- flush: smem rows -> coalesced STG.128 ----
    if (full) {
        float4* o4 = (float4*)(out + (size_t)wbase * 64);
        #pragma unroll
        for (int c = 0; c < 8; c++) {
            int g = c * 32 + l;                  // out float4: sample g>>4, part g&15
            o4[g] = *(const float4*)&R[(g >> 4) * RSTR + (g & 15) * 4];
        }
    } else {
        for (int c = 0; c < 16; c++) {
            int b = wbase + c;
            if (b < B) {
                out[b * 64 + l]      = R[c * RSTR + l];
                out[b * 64 + 32 + l] = R[c * RSTR + 32 + l];
            }
        }
    }

    // ---- inline exact fixup for out-of-range samples (~4e-3) ----
    const bool valid = (wbase + s) < B;
    unsigned fmask = __ballot_sync(0xffffffffu,
                                   (mxf > ZMAX) && valid && (half == 0));
    if (fmask == 0) return;
    const float wca1 = cW[2 * l],        wcv1 = cW[2 * l + 1];
    const float wca2 = cW[2 * (l + 32)], wcv2 = cW[2 * (l + 32) + 1];
    while (fmask) {
        int c = __ffs(fmask) - 1;
        fmask &= fmask - 1;
        int bf = wbase + c;
        float z1 = f1[bf * 32 + l];
        float z2 = f2[bf * 32 + l];
        float acc_a = z1, acc_v = z2;
        #pragma unroll 4
        for (int j = 0; j < 32; j++) {
            float a1 = __shfl_sync(0xffffffffu, z1, j) * 0.125f;
            float a2 = __shfl_sync(0xffffffffu, z2, j) * 0.125f;
            float w1 = __shfl_sync(0xffffffffu, wca1, j);
            float w2 = __shfl_sync(0xffffffffu, wca2, j);
            float w3 = __shfl_sync(0xffffffffu, wcv1, j);
            float w4 = __shfl_sync(0xffffffffu, wcv2, j);
            acc_a = fmaf(tanhfast(z1 * a1), w1, acc_a);
            acc_a = fmaf(tanhfast(z1 * a2), w2, acc_a);
            acc_v = fmaf(tanhfast(z2 * a1), w3, acc_v);
            acc_v = fmaf(tanhfast(z2 * a2), w4, acc_v);
        }
        out[bf * 64 + l]      = 0.1f * fmaxf(acc_a, 0.0f);
        out[bf * 64 + 32 + l] = 0.1f * fmaxf(acc_v, 0.0f);
    }
}

// ---- host: deg-9 odd Chebyshev fit of tanh on |x|<=2 (double precision),
//      with 0.1 output scale and s^(2k+1) (s = 1/8) folded into coefficients.
static Poly make_tanh_poly(void)
{
    const int K = KP;
    const double W = 4.0;                 // w = x^2 in [0, 4]
    double g[KP], th[KP], c[KP];
    for (int i = 0; i < K; i++) {
        th[i] = M_PI * (2.0 * i + 1.0) / (2.0 * K);
        double zh = cos(th[i]);
        double w = 0.5 * W * (zh + 1.0);
        double x = sqrt(w);
        g[i] = tanh(x) / x;
    }
    for (int k = 0; k < K; k++) {
        double ssum = 0.0;
        for (int i = 0; i < K; i++) ssum += g[i] * cos(k * th[i]);
        c[k] = ssum * ((k == 0) ? 1.0 : 2.0) / K;
    }
    double d[KP + 1] = {0}, tp[KP + 1] = {0}, tc[KP + 1] = {0}, tn[KP + 1];
    tp[0] = 1.0;
    tc[1] = 1.0;
    d[0] += c[0];
    d[1] += c[1];
    for (int k = 2; k < K; k++) {
        for (int m = 0; m <= K; m++) tn[m] = -tp[m];
        for (int m = K; m >= 1; m--) tn[m] += 2.0 * tc[m - 1];
        for (int m = 0; m <= K; m++) { tp[m] = tc[m]; tc[m] = tn[m]; d[m] += c[k] * tc[m]; }
    }
    double alpha = 2.0 / W;
    double qd[KP] = {0};
    for (int m = 0; m < K; m++) {
        double binom = 1.0;
        for (int k = 0; k <= m; k++) {
            if (k > 0) binom = binom * (double)(m - k + 1) / (double)k;
            double sgn = ((m - k) & 1) ? -1.0 : 1.0;
            qd[k] += d[m] * binom * pow(alpha, (double)k) * sgn;
        }
    }
    Poly p;
    for (int k = 0; k < KP; k++) {
        double fold = 0.1 * pow(0.125, (double)(2 * k + 1));
        p.q[k] = (float)(qd[k] * fold);
    }
    return p;
}

extern "C" void kernel_launch(void* const* d_in, const int* in_sizes, int n_in,
                              void* d_out, int out_size) {
    const float* f1  = (const float*)d_in[0];
    const float* f2  = (const float*)d_in[1];
    const float* Wca = (const float*)d_in[2];
    const float* Wcv = (const float*)d_in[3];
    float* out = (float*)d_out;

    const int B = in_sizes[0] / 32;
    Poly p = make_tanh_poly();

    // Interleave {Wca[j], Wcv[j]} into __constant__ cW via strided D2D copies.
    void* cw = nullptr;
    cudaGetSymbolAddress(&cw, cW);
    cudaMemcpy2DAsync((char*)cw,     8, Wca, 4, 4, 64, cudaMemcpyDeviceToDevice);
    cudaMemcpy2DAsync((char*)cw + 4, 8, Wcv, 4, 4, 64, cudaMemcpyDeviceToDevice);

    // 64 samples per block (16 per warp, 2 lanes/sample).
    cam_poly_kernel<<<(B + 63) / 64, 128>>>(f1, f2, out, B, p);
}

// round 15
// speedup vs baseline: 1.0849x; 1.0849x over previous
#include <cuda_runtime.h>
#include <math.h>

// CAM_43344809951340 — factored-moment formulation, 2 lanes/sample, 1 wave.
// tanh(s z_i z_j) = sum_k q_k s^(2k+1) z_i^(2k+1) z_j^(2k+1)  (deg-9 odd fit)
//  => row sum = sum_k q'_k z_i^(2k+1) M_k,  M_k = sum_j z_j^(2k+1) W_j.
// Warp owns 16 samples; lane l = sample l&15, half l>>4 (32 elements each).
// Partial moments combined + half-selected by ONE shfl_xor(16) butterfly.
// Sizing: 6250 warps total = 42.2/SM; __launch_bounds__(128,11) (<=46 regs)
// gives 44-warp/SM capacity -> grid 1563 <= 1628 = ONE wave (R13's 1.32-wave
// tail was the regression). Weights: 512B smem table (2-addr broadcast LDS).
// Samples with max|z| > 4 (~4e-3) re-solved exactly inline (tanh.approx).

#define KP   5
#define ZMAX 4.0f
#define RSTR 68                   // smem row stride (floats): 64 data + 4 pad

struct Poly { float q[KP]; };

__constant__ float cW[128];       // interleaved {Wca[j], Wcv[j]} j=0..63

__device__ __forceinline__ float tanhfast(float x) {
    float y; asm("tanh.approx.f32 %0, %1;" : "=f"(y) : "f"(x));
    return y;
}

__global__ __launch_bounds__(128, 11)
void cam_poly_kernel(const float* __restrict__ f1, const float* __restrict__ f2,
                     float* __restrict__ out, int B, Poly pc)
{
    __shared__ float  rows[4][16 * RSTR];   // per-warp: 16 samples x 64
    __shared__ float4 wsh4[32];             // {Wca,Wcv} interleaved, float4 view

    const int tid = threadIdx.x;
    const int wrp = tid >> 5;
    const int l   = tid & 31;

    if (tid < 32) wsh4[tid] = ((const float4*)cW)[tid];
    __syncthreads();

    const int wbase = (blockIdx.x * 4 + wrp) * 16;
    if (wbase >= B) return;
    float* R = rows[wrp];
    const bool full = (wbase + 16 <= B);

    // ---- stage: coalesced LDG.128 -> smem rows (transpose) ----
    if (full) {
        const float4* s1 = (const float4*)(f1 + (size_t)wbase * 32);
        const float4* s2 = (const float4*)(f2 + (size_t)wbase * 32);
        #pragma unroll
        for (int c = 0; c < 4; c++) {
            int g = c * 32 + l;                  // float4 id: sample g>>3, part g&7
            *(float4*)&R[(g >> 3) * RSTR + (g & 7) * 4] = s1[g];
        }
        #pragma unroll
        for (int c = 0; c < 4; c++) {
            int g = c * 32 + l;
            *(float4*)&R[(g >> 3) * RSTR + 32 + (g & 7) * 4] = s2[g];
        }
    } else {
        for (int c = 0; c < 16; c++) {
            int b = wbase + c;
            bool v = b < B;
            R[c * RSTR + l]      = v ? f1[b * 32 + l] : 0.0f;
            R[c * RSTR + 32 + l] = v ? f2[b * 32 + l] : 0.0f;
        }
    }
    __syncwarp();

    const int s    = l & 15;                     // my sample (within warp)
    const int half = l >> 4;                     // 0: elements 0-31, 1: 32-63
    float* myrow = &R[s * RSTR + half * 32];

    // ---- phase 1: partial moments over my 32 elements ----
    float Ma0 = 0.f, Ma1 = 0.f, Ma2 = 0.f, Ma3 = 0.f, Ma4 = 0.f;
    float Mv0 = 0.f, Mv1 = 0.f, Mv2 = 0.f, Mv3 = 0.f, Mv4 = 0.f;
    float mx = 0.0f;

#define ACC(v, wa, wv)                                            \
    do {                                                          \
        float _v = (v);                                           \
        mx = fmaxf(mx, fabsf(_v));                                \
        float _vv = _v * _v;                                      \
        float _p = _v;                                            \
        Ma0 = fmaf(_p, (wa), Ma0); Mv0 = fmaf(_p, (wv), Mv0);     \
        _p *= _vv;                                                \
        Ma1 = fmaf(_p, (wa), Ma1); Mv1 = fmaf(_p, (wv), Mv1);     \
        _p *= _vv;                                                \
        Ma2 = fmaf(_p, (wa), Ma2); Mv2 = fmaf(_p, (wv), Mv2);     \
        _p *= _vv;                                                \
        Ma3 = fmaf(_p, (wa), Ma3); Mv3 = fmaf(_p, (wv), Mv3);     \
        _p *= _vv;                                                \
        Ma4 = fmaf(_p, (wa), Ma4); Mv4 = fmaf(_p, (wv), Mv4);     \
    } while (0)

    #pragma unroll
    for (int jq = 0; jq < 8; jq++) {
        float4 v4 = *(const float4*)&myrow[jq * 4];
        float4 wA = wsh4[half * 16 + jq * 2];        // {wa0,wv0,wa1,wv1}
        float4 wB = wsh4[half * 16 + jq * 2 + 1];    // {wa2,wv2,wa3,wv3}
        ACC(v4.x, wA.x, wA.y);
        ACC(v4.y, wA.z, wA.w);
        ACC(v4.z, wB.x, wB.y);
        ACC(v4.w, wB.z, wB.w);
    }
#undef ACC

    // ---- butterfly: full moments + half-selection in one exchange ----
    // half-0 lane keeps full Ma (output rows 0-31); half-1 keeps full Mv.
    float M0, M1, M2, M3, M4;
#define BFLY(Mk, MaK, MvK, qk)                                     \
    do {                                                           \
        float _send = half ? (MaK) : (MvK);                        \
        float _recv = __shfl_xor_sync(0xffffffffu, _send, 16);     \
        Mk = ((half ? (MvK) : (MaK)) + _recv) * (qk);              \
    } while (0)
    BFLY(M0, Ma0, Mv0, pc.q[0]);
    BFLY(M1, Ma1, Mv1, pc.q[1]);
    BFLY(M2, Ma2, Mv2, pc.q[2]);
    BFLY(M3, Ma3, Mv3, pc.q[3]);
    BFLY(M4, Ma4, Mv4, pc.q[4]);
#undef BFLY
    M0 += 0.1f;    // fold residual slope: A(u) = Horner + 0.1
    float mxf = fmaxf(mx, __shfl_xor_sync(0xffffffffu, mx, 16));

    // ---- phase 2: Horner for my 32 outputs, write back into row ----
    #pragma unroll
    for (int jq = 0; jq < 8; jq++) {
        float4 u4 = *(const float4*)&myrow[jq * 4];
        #pragma unroll
        for (int e = 0; e < 4; e++) {
            float u = (&u4.x)[e];
            float uu = u * u;
            float A = fmaf(M4, uu, M3);
            A = fmaf(A, uu, M2);
            A = fmaf(A, uu, M1);
            A = fmaf(A, uu, M0);
            (&u4.x)[e] = fmaxf(u * A, 0.0f);
        }
        *(float4*)&myrow[jq * 4] = u4;
    }
    __syncwarp();

    // ---- flush: smem rows -> coalesced STG.128 ----
    if (full) {
        float4* o4 = (float4*)(out + (size_t)wbase * 64);
        #pragma unroll
        for (int c = 0; c < 8; c++) {
            int g = c * 32 + l;                  // out float4: sample g>>4, part g&15
            o4[g] = *(const float4*)&R[(g >> 4) * RSTR + (g & 15) * 4];
        }
    } else {
        for (int c = 0; c < 16; c++) {
            int b = wbase + c;
            if (b < B) {
                out[b * 64 + l]      = R[c * RSTR + l];
                out[b * 64 + 32 + l] = R[c * RSTR + 32 + l];
            }
        }
    }

    // ---- inline exact fixup for out-of-range samples (~4e-3) ----
    const bool valid = (wbase + s) < B;
    unsigned fmask = __ballot_sync(0xffffffffu,
                                   (mxf > ZMAX) && valid && (half == 0));
    if (fmask == 0) return;
    const float wca1 = cW[2 * l],        wcv1 = cW[2 * l + 1];
    const float wca2 = cW[2 * (l + 32)], wcv2 = cW[2 * (l + 32) + 1];
    while (fmask) {
        int c = __ffs(fmask) - 1;
        fmask &= fmask - 1;
        int bf = wbase + c;
        float z1 = f1[bf * 32 + l];
        float z2 = f2[bf * 32 + l];
        float acc_a = z1, acc_v = z2;
        #pragma unroll 4
        for (int j = 0; j < 32; j++) {
            float a1 = __shfl_sync(0xffffffffu, z1, j) * 0.125f;
            float a2 = __shfl_sync(0xffffffffu, z2, j) * 0.125f;
            float w1 = __shfl_sync(0xffffffffu, wca1, j);
            float w2 = __shfl_sync(0xffffffffu, wca2, j);
            float w3 = __shfl_sync(0xffffffffu, wcv1, j);
            float w4 = __shfl_sync(0xffffffffu, wcv2, j);
            acc_a = fmaf(tanhfast(z1 * a1), w1, acc_a);
            acc_a = fmaf(tanhfast(z1 * a2), w2, acc_a);
            acc_v = fmaf(tanhfast(z2 * a1), w3, acc_v);
            acc_v = fmaf(tanhfast(z2 * a2), w4, acc_v);
        }
        out[bf * 64 + l]      = 0.1f * fmaxf(acc_a, 0.0f);
        out[bf * 64 + 32 + l] = 0.1f * fmaxf(acc_v, 0.0f);
    }
}

// ---- host: deg-9 odd Chebyshev fit of tanh on |x|<=2 (double precision),
//      with 0.1 output scale and s^(2k+1) (s = 1/8) folded into coefficients.
static Poly make_tanh_poly(void)
{
    const int K = KP;
    const double W = 4.0;                 // w = x^2 in [0, 4]
    double g[KP], th[KP], c[KP];
    for (int i = 0; i < K; i++) {
        th[i] = M_PI * (2.0 * i + 1.0) / (2.0 * K);
        double zh = cos(th[i]);
        double w = 0.5 * W * (zh + 1.0);
        double x = sqrt(w);
        g[i] = tanh(x) / x;
    }
    for (int k = 0; k < K; k++) {
        double ssum = 0.0;
        for (int i = 0; i < K; i++) ssum += g[i] * cos(k * th[i]);
        c[k] = ssum * ((k == 0) ? 1.0 : 2.0) / K;
    }
    double d[KP + 1] = {0}, tp[KP + 1] = {0}, tc[KP + 1] = {0}, tn[KP + 1];
    tp[0] = 1.0;
    tc[1] = 1.0;
    d[0] += c[0];
    d[1] += c[1];
    for (int k = 2; k < K; k++) {
        for (int m = 0; m <= K; m++) tn[m] = -tp[m];
        for (int m = K; m >= 1; m--) tn[m] += 2.0 * tc[m - 1];
        for (int m = 0; m <= K; m++) { tp[m] = tc[m]; tc[m] = tn[m]; d[m] += c[k] * tc[m]; }
    }
    double alpha = 2.0 / W;
    double qd[KP] = {0};
    for (int m = 0; m < K; m++) {
        double binom = 1.0;
        for (int k = 0; k <= m; k++) {
            if (k > 0) binom = binom * (double)(m - k + 1) / (double)k;
            double sgn = ((m - k) & 1) ? -1.0 : 1.0;
            qd[k] += d[m] * binom * pow(alpha, (double)k) * sgn;
        }
    }
    Poly p;
    for (int k = 0; k < KP; k++) {
        double fold = 0.1 * pow(0.125, (double)(2 * k + 1));
        p.q[k] = (float)(qd[k] * fold);
    }
    return p;
}

extern "C" void kernel_launch(void* const* d_in, const int* in_sizes, int n_in,
                              void* d_out, int out_size) {
    const float* f1  = (const float*)d_in[0];
    const float* f2  = (const float*)d_in[1];
    const float* Wca = (const float*)d_in[2];
    const float* Wcv = (const float*)d_in[3];
    float* out = (float*)d_out;

    const int B = in_sizes[0] / 32;
    Poly p = make_tanh_poly();

    // Interleave {Wca[j], Wcv[j]} into __constant__ cW via strided D2D copies.
    void* cw = nullptr;
    cudaGetSymbolAddress(&cw, cW);
    cudaMemcpy2DAsync((char*)cw,     8, Wca, 4, 4, 64, cudaMemcpyDeviceToDevice);
    cudaMemcpy2DAsync((char*)cw + 4, 8, Wcv, 4, 4, 64, cudaMemcpyDeviceToDevice);

    // 64 samples per block (16 per warp, 2 lanes/sample); single wave:
    // grid 1563 <= 11 blocks/SM * 148 SMs = 1628.
    cam_poly_kernel<<<(B + 63) / 64, 128>>>(f1, f2, out, B, p);
}

// round 17
// speedup vs baseline: 1.5333x; 1.4133x over previous
#include <cuda_runtime.h>
#include <cstdint>
#include <math.h>

// CAM_43344809951340 — factored moments + cp.async double-buffered pipeline.
// tanh(s z_i z_j) = sum_k q_k s^(2k+1) z_i^(2k+1) z_j^(2k+1)  (deg-9 odd fit)
//  => row sum = sum_k q'_k z_i^(2k+1) M_k,  M_k = sum_j z_j^(2k+1) W_j.
// 16-sample tiles; lane l = sample l&15, half l>>4; one shfl_xor(16)
// butterfly combines+selects moments. Weights on the const port (2-address
// LDC, cheap) — NOT smem (R14's L1 flood). Each warp ping-pongs two tiles:
// cp.async.cg prefetch of tile n+1 overlaps compute of tile n, removing the
// 577-cyc LDG latency from the critical path. 24 warps/SM, single wave.
// Samples with max|z| > 4 (~4e-3) re-solved exactly inline (tanh.approx).

#define KP   5
#define ZMAX 4.0f
#define RSTR 68                   // smem row stride (floats): 64 data + 4 pad
#define TS   16                   // samples per tile

struct Poly { float q[KP]; };

__constant__ float cW[128];       // interleaved {Wca[j], Wcv[j]} j=0..63

__device__ __forceinline__ float tanhfast(float x) {
    float y; asm("tanh.approx.f32 %0, %1;" : "=f"(y) : "f"(x));
    return y;
}
__device__ __forceinline__ void cp16(unsigned int saddr, const void* g) {
    asm volatile("cp.async.cg.shared.global [%0], [%1], 16;\n"
                 :: "r"(saddr), "l"(g));
}
__device__ __forceinline__ void cp_commit() {
    asm volatile("cp.async.commit_group;\n");
}

__global__ __launch_bounds__(128, 6)
void cam_poly_kernel(const float* __restrict__ f1, const float* __restrict__ f2,
                     float* __restrict__ out, int B, Poly pc)
{
    __shared__ float rows[4][2][TS * RSTR];   // per-warp ping-pong tile buffers

    const int tid = threadIdx.x;
    const int wrp = tid >> 5;
    const int l   = tid & 31;
    const int ntiles = (B + TS - 1) / TS;
    const int nw  = gridDim.x * 4;
    const int wid = blockIdx.x * 4 + wrp;

    // ---- async prefetch of one tile into buffer buf (no-op commit if OOB) ----
    auto prefetch = [&](int buf, int t) {
        if (t < ntiles) {
            int base = t * TS;
            if (base + TS <= B) {
                const float4* s1 = (const float4*)(f1 + (size_t)base * 32);
                const float4* s2 = (const float4*)(f2 + (size_t)base * 32);
                float* R = rows[wrp][buf];
                #pragma unroll
                for (int c = 0; c < 4; c++) {
                    int g = c * 32 + l;           // f4 id: sample g>>3, part g&7
                    cp16((unsigned int)__cvta_generic_to_shared(
                             &R[(g >> 3) * RSTR + (g & 7) * 4]), s1 + g);
                }
                #pragma unroll
                for (int c = 0; c < 4; c++) {
                    int g = c * 32 + l;
                    cp16((unsigned int)__cvta_generic_to_shared(
                             &R[(g >> 3) * RSTR + 32 + (g & 7) * 4]), s2 + g);
                }
            }
        }
        cp_commit();
    };

    prefetch(0, wid);
    prefetch(1, wid + nw);

    int cur = 0;
    for (int t = wid; t < ntiles; t += nw, cur ^= 1) {
        asm volatile("cp.async.wait_group 1;\n" ::: "memory");
        __syncwarp();

        float* R = rows[wrp][cur];
        const int base = t * TS;
        const bool full = (base + TS <= B);
        if (!full) {                 // rare partial tile: scalar staged load
            for (int c = 0; c < TS; c++) {
                int b = base + c;
                bool v = b < B;
                R[c * RSTR + l]      = v ? f1[b * 32 + l] : 0.0f;
                R[c * RSTR + 32 + l] = v ? f2[b * 32 + l] : 0.0f;
            }
            __syncwarp();
        }

        const int s    = l & 15;     // my sample (within tile)
        const int half = l >> 4;     // 0: elements 0-31, 1: 32-63
        float* myrow = &R[s * RSTR + half * 32];

        // ---- phase 1: partial moments over my 32 elements ----
        float Ma0 = 0.f, Ma1 = 0.f, Ma2 = 0.f, Ma3 = 0.f, Ma4 = 0.f;
        float Mv0 = 0.f, Mv1 = 0.f, Mv2 = 0.f, Mv3 = 0.f, Mv4 = 0.f;
        float mx = 0.0f;

#define ACC(v, wa, wv)                                            \
        do {                                                      \
            float _v = (v);                                       \
            mx = fmaxf(mx, fabsf(_v));                            \
            float _vv = _v * _v;                                  \
            float _p = _v;                                        \
            Ma0 = fmaf(_p, (wa), Ma0); Mv0 = fmaf(_p, (wv), Mv0); \
            _p *= _vv;                                            \
            Ma1 = fmaf(_p, (wa), Ma1); Mv1 = fmaf(_p, (wv), Mv1); \
            _p *= _vv;                                            \
            Ma2 = fmaf(_p, (wa), Ma2); Mv2 = fmaf(_p, (wv), Mv2); \
            _p *= _vv;                                            \
            Ma3 = fmaf(_p, (wa), Ma3); Mv3 = fmaf(_p, (wv), Mv3); \
            _p *= _vv;                                            \
            Ma4 = fmaf(_p, (wa), Ma4); Mv4 = fmaf(_p, (wv), Mv4); \
        } while (0)

        #pragma unroll
        for (int jq = 0; jq < 8; jq++) {
            float4 v4 = *(const float4*)&myrow[jq * 4];
            // const port: 2 distinct addresses per warp (one per half)
            float4 wA = ((const float4*)cW)[half * 16 + jq * 2];
            float4 wB = ((const float4*)cW)[half * 16 + jq * 2 + 1];
            ACC(v4.x, wA.x, wA.y);
            ACC(v4.y, wA.z, wA.w);
            ACC(v4.z, wB.x, wB.y);
            ACC(v4.w, wB.z, wB.w);
        }
#undef ACC

        // ---- butterfly: full moments + half-selection in one exchange ----
        float M0, M1, M2, M3, M4;
#define BFLY(Mk, MaK, MvK, qk)                                    \
        do {                                                      \
            float _send = half ? (MaK) : (MvK);                   \
            float _recv = __shfl_xor_sync(0xffffffffu, _send, 16);\
            Mk = ((half ? (MvK) : (MaK)) + _recv) * (qk);         \
        } while (0)
        BFLY(M0, Ma0, Mv0, pc.q[0]);
        BFLY(M1, Ma1, Mv1, pc.q[1]);
        BFLY(M2, Ma2, Mv2, pc.q[2]);
        BFLY(M3, Ma3, Mv3, pc.q[3]);
        BFLY(M4, Ma4, Mv4, pc.q[4]);
#undef BFLY
        M0 += 0.1f;                  // fold residual slope
        float mxf = fmaxf(mx, __shfl_xor_sync(0xffffffffu, mx, 16));

        // ---- phase 2: Horner for my 32 outputs, write back into row ----
        #pragma unroll
        for (int jq = 0; jq < 8; jq++) {
            float4 u4 = *(const float4*)&myrow[jq * 4];
            #pragma unroll
            for (int e = 0; e < 4; e++) {
                float u = (&u4.x)[e];
                float uu = u * u;
                float A = fmaf(M4, uu, M3);
                A = fmaf(A, uu, M2);
                A = fmaf(A, uu, M1);
                A = fmaf(A, uu, M0);
                (&u4.x)[e] = fmaxf(u * A, 0.0f);
            }
            *(float4*)&myrow[jq * 4] = u4;
        }
        __syncwarp();

        // ---- flush: smem rows -> coalesced STG.128 ----
        if (full) {
            float4* o4 = (float4*)(out + (size_t)base * 64);
            #pragma unroll
            for (int c = 0; c < 8; c++) {
                int g = c * 32 + l;  // out f4: sample g>>4, part g&15
                o4[g] = *(const float4*)&R[(g >> 4) * RSTR + (g & 15) * 4];
            }
        } else {
            for (int c = 0; c < TS; c++) {
                int b = base + c;
                if (b < B) {
                    out[b * 64 + l]      = R[c * RSTR + l];
                    out[b * 64 + 32 + l] = R[c * RSTR + 32 + l];
                }
            }
        }

        // ---- inline exact fixup for out-of-range samples (~4e-3) ----
        const bool valid = (base + s) < B;
        unsigned fmask = __ballot_sync(0xffffffffu,
                                       (mxf > ZMAX) && valid && (half == 0));
        while (fmask) {
            int c = __ffs(fmask) - 1;
            fmask &= fmask - 1;
            int bf = base + c;
            float z1 = f1[bf * 32 + l];
            float z2 = f2[bf * 32 + l];
            float wca1 = cW[2 * l],        wcv1 = cW[2 * l + 1];
            float wca2 = cW[2 * (l + 32)], wcv2 = cW[2 * (l + 32) + 1];
            float acc_a = z1, acc_v = z2;
            #pragma unroll 4
            for (int j = 0; j < 32; j++) {
                float a1 = __shfl_sync(0xffffffffu, z1, j) * 0.125f;
                float a2 = __shfl_sync(0xffffffffu, z2, j) * 0.125f;
                float w1 = __shfl_sync(0xffffffffu, wca1, j);
                float w2 = __shfl_sync(0xffffffffu, wca2, j);
                float w3 = __shfl_sync(0xffffffffu, wcv1, j);
                float w4 = __shfl_sync(0xffffffffu, wcv2, j);
                acc_a = fmaf(tanhfast(z1 * a1), w1, acc_a);
                acc_a = fmaf(tanhfast(z1 * a2), w2, acc_a);
                acc_v = fmaf(tanhfast(z2 * a1), w3, acc_v);
                acc_v = fmaf(tanhfast(z2 * a2), w4, acc_v);
            }
            out[bf * 64 + l]      = 0.1f * fmaxf(acc_a, 0.0f);
            out[bf * 64 + 32 + l] = 0.1f * fmaxf(acc_v, 0.0f);
        }
        __syncwarp();

        // refill the buffer we just finished with tile t + 2*nw
        prefetch(cur, t + 2 * nw);
    }
}

// ---- host: deg-9 odd Chebyshev fit of tanh on |x|<=2 (double precision),
//      with 0.1 output scale and s^(2k+1) (s = 1/8) folded into coefficients.
static Poly make_tanh_poly(void)
{
    const int K = KP;
    const double W = 4.0;                 // w = x^2 in [0, 4]
    double g[KP], th[KP], c[KP];
    for (int i = 0; i < K; i++) {
        th[i] = M_PI * (2.0 * i + 1.0) / (2.0 * K);
        double zh = cos(th[i]);
        double w = 0.5 * W * (zh + 1.0);
        double x = sqrt(w);
        g[i] = tanh(x) / x;
    }
    for (int k = 0; k < K; k++) {
        double ssum = 0.0;
        for (int i = 0; i < K; i++) ssum += g[i] * cos(k * th[i]);
        c[k] = ssum * ((k == 0) ? 1.0 : 2.0) / K;
    }
    double d[KP + 1] = {0}, tp[KP + 1] = {0}, tc[KP + 1] = {0}, tn[KP + 1];
    tp[0] = 1.0;
    tc[1] = 1.0;
    d[0] += c[0];
    d[1] += c[1];
    for (int k = 2; k < K; k++) {
        for (int m = 0; m <= K; m++) tn[m] = -tp[m];
        for (int m = K; m >= 1; m--) tn[m] += 2.0 * tc[m - 1];
        for (int m = 0; m <= K; m++) { tp[m] = tc[m]; tc[m] = tn[m]; d[m] += c[k] * tc[m]; }
    }
    double alpha = 2.0 / W;
    double qd[KP] = {0};
    for (int m = 0; m < K; m++) {
        double binom = 1.0;
        for (int k = 0; k <= m; k++) {
            if (k > 0) binom = binom * (double)(m - k + 1) / (double)k;
            double sgn = ((m - k) & 1) ? -1.0 : 1.0;
            qd[k] += d[m] * binom * pow(alpha, (double)k) * sgn;
        }
    }
    Poly p;
    for (int k = 0; k < KP; k++) {
        double fold = 0.1 * pow(0.125, (double)(2 * k + 1));
        p.q[k] = (float)(qd[k] * fold);
    }
    return p;
}

extern "C" void kernel_launch(void* const* d_in, const int* in_sizes, int n_in,
                              void* d_out, int out_size) {
    const float* f1  = (const float*)d_in[0];
    const float* f2  = (const float*)d_in[1];
    const float* Wca = (const float*)d_in[2];
    const float* Wcv = (const float*)d_in[3];
    float* out = (float*)d_out;

    const int B = in_sizes[0] / 32;
    Poly p = make_tanh_poly();

    // Interleave {Wca[j], Wcv[j]} into __constant__ cW via strided D2D copies.
    void* cw = nullptr;
    cudaGetSymbolAddress(&cw, cW);
    cudaMemcpy2DAsync((char*)cw,     8, Wca, 4, 4, 64, cudaMemcpyDeviceToDevice);
    cudaMemcpy2DAsync((char*)cw + 4, 8, Wcv, 4, 4, 64, cudaMemcpyDeviceToDevice);

    // 6 blocks/SM x 148 SMs = 888 blocks (3552 warps), ping-pong pipelined
    // over ceil(B/16) tiles with static stride.
    int ntiles = (B + TS - 1) / TS;
    int grid = (ntiles + 3) / 4;
    if (grid > 888) grid = 888;
    cam_poly_kernel<<<grid, 128>>>(f1, f2, out, B, p);
}